// round 15
// baseline (speedup 1.0000x reference)
#include <cuda_runtime.h>
#include <cstdint>

#define H128 128
static const int CAP_N = 50000;
static const int CAP_E = 800000;

// ---------------- scratch (device globals; no allocation allowed) ----------------
__device__ float g_h  [CAP_N * H128];
__device__ float g_acc[CAP_N * H128];
__device__ float g_A1 [CAP_N * H128];
__device__ float g_A2 [CAP_N * H128];
__device__ float g_A3 [CAP_N * H128];
__device__ float g_B2 [CAP_N * H128];
__device__ float g_B3 [CAP_N * H128];
__device__ float g_e  [CAP_E * H128];
__device__ float g_tmp[CAP_E * H128];
__device__ float g_wc [376832];          // pre-converted tf32 weights

// ---------------- L2 residency policies ----------------
__device__ __forceinline__ uint64_t pol_ef() {
    uint64_t p;
    asm("createpolicy.fractional.L2::evict_first.b64 %0, 1.0;" : "=l"(p));
    return p;
}
__device__ __forceinline__ uint64_t pol_el() {
    uint64_t p;
    asm("createpolicy.fractional.L2::evict_last.b64 %0, 1.0;" : "=l"(p));
    return p;
}

// ---------------- generic helpers ----------------
__device__ __forceinline__ uint32_t smem_u32(const void* p) {
    uint32_t a;
    asm("{ .reg .u64 t; cvta.to.shared.u64 t, %1; cvt.u32.u64 %0, t; }" : "=r"(a) : "l"(p));
    return a;
}
__device__ __forceinline__ void red_add_v4(float* p, const float* v) {
    asm volatile("red.global.add.v4.f32 [%0], {%1, %2, %3, %4};"
                 :: "l"(p), "f"(v[0]), "f"(v[1]), "f"(v[2]), "f"(v[3]) : "memory");
}
__device__ __forceinline__ void ld4(float* d, const float* p) {
    float4 v = *reinterpret_cast<const float4*>(p);
    d[0] = v.x; d[1] = v.y; d[2] = v.z; d[3] = v.w;
}
__device__ __forceinline__ void ld4_h(float* d, const float* p, uint64_t pol) {
    asm volatile("ld.global.L2::cache_hint.v4.f32 {%0,%1,%2,%3}, [%4], %5;"
                 : "=f"(d[0]), "=f"(d[1]), "=f"(d[2]), "=f"(d[3]) : "l"(p), "l"(pol));
}
__device__ __forceinline__ void lds4(float* d, uint32_t a) {
    asm volatile("ld.shared.v4.f32 {%0,%1,%2,%3}, [%4];"
                 : "=f"(d[0]), "=f"(d[1]), "=f"(d[2]), "=f"(d[3]) : "r"(a));
}
__device__ __forceinline__ void st4(float* p, const float* d) {
    float4 v; v.x = d[0]; v.y = d[1]; v.z = d[2]; v.w = d[3];
    *reinterpret_cast<float4*>(p) = v;
}
__device__ __forceinline__ void st4_h(float* p, const float* d, uint64_t pol) {
    asm volatile("st.global.L2::cache_hint.v4.f32 [%0], {%1,%2,%3,%4}, %5;"
                 :: "l"(p), "f"(d[0]), "f"(d[1]), "f"(d[2]), "f"(d[3]), "l"(pol) : "memory");
}
__device__ __forceinline__ void st2_h(float* p, float a, float b, int hint) {
    if (hint == 2) {
        uint64_t pol = pol_el();
        asm volatile("st.global.L2::cache_hint.v2.f32 [%0], {%1,%2}, %3;"
                     :: "l"(p), "f"(a), "f"(b), "l"(pol) : "memory");
    } else if (hint == 1) {
        uint64_t pol = pol_ef();
        asm volatile("st.global.L2::cache_hint.v2.f32 [%0], {%1,%2}, %3;"
                     :: "l"(p), "f"(a), "f"(b), "l"(pol) : "memory");
    } else {
        float2 v; v.x = a; v.y = b;
        *reinterpret_cast<float2*>(p) = v;
    }
}
// 16B async copy gmem->smem (plain form: cache_hint on LDGSTS traps on sm_103)
__device__ __forceinline__ void cpa16(uint32_t dst, const float* src) {
    asm volatile("cp.async.ca.shared.global [%0], [%1], 16;"
                 :: "r"(dst), "l"(src) : "memory");
}
__device__ __forceinline__ void cpa_commit() {
    asm volatile("cp.async.commit_group;" ::: "memory");
}
__device__ __forceinline__ void cpa_wait1() {
    asm volatile("cp.async.wait_group 1;" ::: "memory");
}
__device__ __forceinline__ void cpa_wait0() {
    asm volatile("cp.async.wait_group 0;" ::: "memory");
}
__device__ __forceinline__ uint32_t to_tf32(float x) {
    uint32_t r;
    asm("cvt.rna.tf32.f32 %0, %1;" : "=r"(r) : "f"(x));
    return r;
}
__device__ __forceinline__ void mma_tf32(float d[4], const uint32_t a[4], const uint32_t b[2],
                                         const float c[4]) {
    asm volatile(
        "mma.sync.aligned.m16n8k8.row.col.f32.tf32.tf32.f32 "
        "{%0,%1,%2,%3}, {%4,%5,%6,%7}, {%8,%9}, {%10,%11,%12,%13};"
        : "=f"(d[0]), "=f"(d[1]), "=f"(d[2]), "=f"(d[3])
        : "r"(a[0]), "r"(a[1]), "r"(a[2]), "r"(a[3]),
          "r"(b[0]), "r"(b[1]),
          "f"(c[0]), "f"(c[1]), "f"(c[2]), "f"(c[3]));
}

// ---------------- weight pre-conversion to tf32 ----------------
__global__ void conv_tf32_kernel(const float* __restrict__ src, float* __restrict__ dst, int n4) {
    int i = blockIdx.x * 256 + threadIdx.x;
    if (i < n4) {
        float4 v = reinterpret_cast<const float4*>(src)[i];
        uint4 u; u.x = to_tf32(v.x); u.y = to_tf32(v.y); u.z = to_tf32(v.z); u.w = to_tf32(v.w);
        reinterpret_cast<uint4*>(dst)[i] = u;
    }
}

// ---------------- shared GEMM tile machinery (256 threads, 128x128 tile) ----------------
static const int AS_STRIDE = 132;
static const int WS_STRIDE = 136;
static const int SM_W = 128 * AS_STRIDE;            // 16896 floats = 67584 B
static const int W_CHUNK = 32 * WS_STRIDE;          // 4352 floats per 32-k chunk buffer
static const int SM_FLOATS = SM_W + 2 * W_CHUNK;    // + 8704 floats = 34816 B
static const int SM_BYTES = SM_FLOATS * 4;          // 102400 B -> 2 CTAs/SM

__device__ __forceinline__ void load_tile_tf32(const float* __restrict__ A, int M, int brow,
                                               uint32_t* as, int t, int ef) {
    const float4* A4 = reinterpret_cast<const float4*>(A);
    uint64_t pol = ef ? pol_ef() : 0;
    #pragma unroll
    for (int j = 0; j < 16; j++) {
        int flat = j * 256 + t;
        int row = flat >> 5, k4 = flat & 31;
        int gr = brow + row;
        float v[4] = {0.f, 0.f, 0.f, 0.f};
        if (gr < M) {
            const float* p = reinterpret_cast<const float*>(A4 + (size_t)gr * 32 + k4);
            if (ef) ld4_h(v, p, pol); else ld4(v, p);
        }
        uint4 u; u.x = to_tf32(v[0]); u.y = to_tf32(v[1]); u.z = to_tf32(v[2]); u.w = to_tf32(v[3]);
        *reinterpret_cast<uint4*>(as + row * AS_STRIDE + k4 * 4) = u;
    }
}

// async-load one 32-k W chunk (pre-converted tf32) into smem buffer
__device__ __forceinline__ void cpa_chunk_w(uint32_t wb_addr, const float* __restrict__ W,
                                            int ch, int t) {
    #pragma unroll
    for (int j = 0; j < 4; j++) {
        int flat = j * 256 + t;
        int k = flat >> 5, c4 = flat & 31;
        cpa16(wb_addr + (uint32_t)(k * WS_STRIDE + c4 * 4) * 4,
              W + (size_t)(ch * 32 + k) * 128 + c4 * 4);
    }
}

// dacc = Atile @ W ; W pre-converted tf32; 4 x 32-k chunks, cp.async double-buffered.
__device__ __forceinline__ void gemm_core_256(const uint32_t* as, uint32_t* wsm,
                                              const float* __restrict__ W,
                                              float dacc[2][8][4], int t) {
    const int wid = t >> 5, lane = t & 31;
    const int gid = lane >> 2, tig = lane & 3;
    const int m0 = (wid & 3) * 32, n0 = (wid >> 2) * 64;
    const uint32_t wsm_addr = smem_u32(wsm);

    #pragma unroll
    for (int mi = 0; mi < 2; mi++)
        #pragma unroll
        for (int ni = 0; ni < 8; ni++)
            #pragma unroll
            for (int q = 0; q < 4; q++) dacc[mi][ni][q] = 0.f;

    cpa_chunk_w(wsm_addr, W, 0, t);
    cpa_commit();

    #pragma unroll 1
    for (int ch = 0; ch < 4; ch++) {
        if (ch < 3) {
            cpa_chunk_w(wsm_addr + (uint32_t)(((ch + 1) & 1) * W_CHUNK) * 4, W, ch + 1, t);
            cpa_commit();
            cpa_wait1();
        } else {
            cpa_wait0();
        }
        __syncthreads();
        const uint32_t* wb = wsm + (ch & 1) * W_CHUNK;

        #pragma unroll
        for (int ks = 0; ks < 4; ks++) {
            const int k0 = ks * 8;
            uint32_t af[2][4];
            #pragma unroll
            for (int mi = 0; mi < 2; mi++) {
                const uint32_t* pa = as + (m0 + mi * 16 + gid) * AS_STRIDE + ch * 32 + k0;
                af[mi][0] = pa[tig];
                af[mi][1] = pa[8 * AS_STRIDE + tig];
                af[mi][2] = pa[tig + 4];
                af[mi][3] = pa[8 * AS_STRIDE + tig + 4];
            }
            uint32_t bf[8][2];
            #pragma unroll
            for (int ni = 0; ni < 8; ni++) {
                const uint32_t* pb = wb + (k0 + tig) * WS_STRIDE + n0 + ni * 8 + gid;
                bf[ni][0] = pb[0];
                bf[ni][1] = pb[4 * WS_STRIDE];
            }
            #pragma unroll
            for (int mi = 0; mi < 2; mi++)
                #pragma unroll
                for (int ni = 0; ni < 8; ni++)
                    mma_tf32(dacc[mi][ni], af[mi], bf[ni], dacc[mi][ni]);
        }
        __syncthreads();
    }
}

__device__ __forceinline__ void store_dacc_smem(float* ebt, float dacc[2][8][4],
                                                const float* __restrict__ bias, int t) {
    const int wid = t >> 5, lane = t & 31;
    const int gid = lane >> 2, tig = lane & 3;
    const int m0 = (wid & 3) * 32, n0 = (wid >> 2) * 64;
    #pragma unroll
    for (int ni = 0; ni < 8; ni++) {
        const int col = n0 + ni * 8 + 2 * tig;
        float b0 = 0.f, b1 = 0.f;
        if (bias) { b0 = bias[col]; b1 = bias[col + 1]; }
        #pragma unroll
        for (int mi = 0; mi < 2; mi++) {
            const int row = m0 + mi * 16 + gid;
            float2 v0; v0.x = dacc[mi][ni][0] + b0; v0.y = dacc[mi][ni][1] + b1;
            float2 v1; v1.x = dacc[mi][ni][2] + b0; v1.y = dacc[mi][ni][3] + b1;
            *reinterpret_cast<float2*>(ebt + row * AS_STRIDE + col) = v0;
            *reinterpret_cast<float2*>(ebt + (row + 8) * AS_STRIDE + col) = v1;
        }
    }
}

__device__ __forceinline__ void store_dacc_global(float* O, float dacc[2][8][4],
                                                  const float* __restrict__ bias,
                                                  int brow, int M, int oh, int t) {
    const int wid = t >> 5, lane = t & 31;
    const int gid = lane >> 2, tig = lane & 3;
    const int m0 = (wid & 3) * 32, n0 = (wid >> 2) * 64;
    #pragma unroll
    for (int ni = 0; ni < 8; ni++) {
        const int col = n0 + ni * 8 + 2 * tig;
        float b0 = 0.f, b1 = 0.f;
        if (bias) { b0 = bias[col]; b1 = bias[col + 1]; }
        #pragma unroll
        for (int mi = 0; mi < 2; mi++) {
            const int row0 = brow + m0 + mi * 16 + gid;
            if (row0 < M)
                st2_h(O + (size_t)row0 * 128 + col, dacc[mi][ni][0] + b0, dacc[mi][ni][1] + b1, oh);
            if (row0 + 8 < M)
                st2_h(O + (size_t)(row0 + 8) * 128 + col, dacc[mi][ni][2] + b0, dacc[mi][ni][3] + b1, oh);
        }
    }
}

// ---------------- standalone multi-weight GEMM (weight = blockIdx.y) ----------------
struct G5 {
    const float* W[5];
    const float* B[5];
    float*       O[5];
    int OH[5];
    int nw;
    int IH;
};

__global__ void __launch_bounds__(256, 2) gemm_mma_kernel(
    const float* __restrict__ A, G5 g, int M)
{
    extern __shared__ float sm[];
    uint32_t* as  = reinterpret_cast<uint32_t*>(sm);
    uint32_t* wsm = reinterpret_cast<uint32_t*>(sm + SM_W);
    const int t = threadIdx.x;
    const int brow = blockIdx.x * 128;
    const int w = blockIdx.y;

    load_tile_tf32(A, M, brow, as, t, g.IH);

    float dacc[2][8][4];
    gemm_core_256(as, wsm, g.W[w], dacc, t);
    store_dacc_global(g.O[w], dacc, g.B[w], brow, M, g.OH[w], t);
}

// ---------------- embed stage1: out = LN(relu(in @ W + b)) (warp per row) ----------------
__global__ void __launch_bounds__(256) embed_ln_kernel(
    const float* __restrict__ in, const float* __restrict__ W, const float* __restrict__ bias,
    const float* __restrict__ lng, const float* __restrict__ lnb,
    float* __restrict__ out, int M, int Kin)
{
    const int w = blockIdx.x * 8 + (threadIdx.x >> 5);
    const int lane = threadIdx.x & 31;
    if (w >= M) return;
    const float* xr = in + (size_t)w * Kin;
    float x0 = (lane < Kin) ? xr[lane] : 0.f;
    float x1 = (lane + 32 < Kin) ? xr[lane + 32] : 0.f;

    float a[4];
    ld4(a, bias + lane * 4);
    for (int k = 0; k < Kin; k++) {
        float xk = __shfl_sync(0xffffffffu, (k < 32) ? x0 : x1, k & 31);
        float4 wv = *reinterpret_cast<const float4*>(W + k * 128 + lane * 4);
        a[0] = fmaf(xk, wv.x, a[0]);
        a[1] = fmaf(xk, wv.y, a[1]);
        a[2] = fmaf(xk, wv.z, a[2]);
        a[3] = fmaf(xk, wv.w, a[3]);
    }
    float s = 0.f, q = 0.f;
    #pragma unroll
    for (int i = 0; i < 4; i++) {
        a[i] = fmaxf(a[i], 0.f);
        s += a[i]; q = fmaf(a[i], a[i], q);
    }
    #pragma unroll
    for (int o = 16; o; o >>= 1) {
        s += __shfl_xor_sync(0xffffffffu, s, o);
        q += __shfl_xor_sync(0xffffffffu, q, o);
    }
    const float inv = 1.f / 128.f;
    float m = s * inv;
    float is = rsqrtf(fmaxf(q * inv - m * m, 0.f) + 1e-5f);
    float gg[4], gb[4], o4[4];
    ld4(gg, lng + lane * 4); ld4(gb, lnb + lane * 4);
    #pragma unroll
    for (int i = 0; i < 4; i++) o4[i] = (a[i] - m) * is * gg[i] + gb[i];
    uint64_t pef = pol_ef();
    st4_h(out + (size_t)w * 128 + lane * 4, o4, pef);
}

// ---------------- fused edge layer: B1e GEMM + gated edge update (cp.async pipelined) ----
__global__ void __launch_bounds__(256, 2) edge_fused_kernel(
    const int* __restrict__ rows, const int* __restrict__ cols,
    float* __restrict__ e, const float* __restrict__ W, const float* __restrict__ bias,
    const float* __restrict__ A2, const float* __restrict__ A3,
    const float* __restrict__ B2, const float* __restrict__ B3,
    const float* __restrict__ lng, const float* __restrict__ lnb,
    float* __restrict__ acc, int E_)
{
    extern __shared__ float sm[];
    uint32_t* as  = reinterpret_cast<uint32_t*>(sm);
    uint32_t* wsm = reinterpret_cast<uint32_t*>(sm + SM_W);
    const int t = threadIdx.x;
    const int wid = t >> 5, lane = t & 31;
    const int brow = blockIdx.x * 128;

    // stage 1: b1e tile = e_tile @ W + bias
    load_tile_tf32(e, E_, brow, as, t, 1);
    float dacc[2][8][4];
    gemm_core_256(as, wsm, W, dacc, t);
    __syncthreads();
    float* ebt = sm;
    store_dacc_smem(ebt, dacc, bias, t);
    __syncthreads();

    // stage 2: warp per edge with cp.async double-buffered B-gather prefetch.
    int idx;
    {
        int epos = brow + wid * 16 + (lane & 15);
        if (epos >= E_) epos = E_ - 1;
        const int* bp = (lane < 16) ? rows : cols;
        idx = bp[epos];
    }

    const uint64_t pef = pol_ef();
    const uint64_t pel = pol_el();
    const uint32_t pfw = smem_u32(sm) + (uint32_t)SM_W * 4 + (uint32_t)wid * 4096;
    const uint32_t loff = (uint32_t)lane * 16;

    {
        int r0 = __shfl_sync(0xffffffffu, idx, 0);
        int c0 = __shfl_sync(0xffffffffu, idx, 16);
        uint32_t b = pfw + loff;
        cpa16(b,        B2 + (size_t)r0 * 128 + lane * 4);
        cpa16(b + 512,  B3 + (size_t)r0 * 128 + lane * 4);
        cpa16(b + 1024, B2 + (size_t)c0 * 128 + lane * 4);
        cpa16(b + 1536, B3 + (size_t)c0 * 128 + lane * 4);
        cpa_commit();
    }

    float gg[4], gb[4];
    ld4(gg, lng + lane * 4); ld4(gb, lnb + lane * 4);
    const float inv = 1.f / 128.f;

    #pragma unroll 1
    for (int i = 0; i < 16; i++) {
        const int le = wid * 16 + i;
        const int w = brow + le;
        if (w >= E_) break;
        const int r = __shfl_sync(0xffffffffu, idx, i);
        const int c = __shfl_sync(0xffffffffu, idx, 16 + i);

        {
            const int ipn = (i < 15) ? i + 1 : 15;
            int rn = __shfl_sync(0xffffffffu, idx, ipn);
            int cn = __shfl_sync(0xffffffffu, idx, 16 + ipn);
            uint32_t b = pfw + ((i + 1) & 1) * 2048 + loff;
            cpa16(b,        B2 + (size_t)rn * 128 + lane * 4);
            cpa16(b + 512,  B3 + (size_t)rn * 128 + lane * 4);
            cpa16(b + 1024, B2 + (size_t)cn * 128 + lane * 4);
            cpa16(b + 1536, B3 + (size_t)cn * 128 + lane * 4);
            cpa_commit();
        }

        const size_t eo = (size_t)w * 128 + lane * 4;
        const size_t ro = (size_t)r * 128 + lane * 4;
        const size_t co = (size_t)c * 128 + lane * 4;

        float a2r[4], a3c[4], ev[4], b1[4];
        ld4_h(a2r, A2 + ro, pel);
        ld4_h(a3c, A3 + co, pel);
        ld4_h(ev, e + eo, pef);
        ld4(b1, ebt + le * AS_STRIDE + lane * 4);

        cpa_wait1();
        float b2r[4], b3r[4], b2c[4], b3c[4];
        const uint32_t bb = pfw + (i & 1) * 2048 + loff;
        lds4(b2r, bb);
        lds4(b3r, bb + 512);
        lds4(b2c, bb + 1024);
        lds4(b3c, bb + 1536);

        float gji[4], gik[4];
        float s1 = 0.f, q1 = 0.f, s2 = 0.f, q2 = 0.f;
        #pragma unroll
        for (int j = 0; j < 4; j++) {
            float u = fmaxf(b1[j] + b2r[j] + b3c[j], 0.f);
            float v = fmaxf(b1[j] + b2c[j] + b3r[j], 0.f);
            gji[j] = u; gik[j] = v;
            s1 += u; q1 = fmaf(u, u, q1);
            s2 += v; q2 = fmaf(v, v, q2);
        }
        #pragma unroll
        for (int o = 16; o; o >>= 1) {
            s1 += __shfl_xor_sync(0xffffffffu, s1, o);
            q1 += __shfl_xor_sync(0xffffffffu, q1, o);
            s2 += __shfl_xor_sync(0xffffffffu, s2, o);
            q2 += __shfl_xor_sync(0xffffffffu, q2, o);
        }
        float m1 = s1 * inv, m2 = s2 * inv;
        float is1 = rsqrtf(fmaxf(q1 * inv - m1 * m1, 0.f) + 1e-5f);
        float is2 = rsqrtf(fmaxf(q2 * inv - m2 * m2, 0.f) + 1e-5f);

        float eji[4], sg1[4], sg2[4];
        float t1 = 0.f, t2 = 0.f;
        #pragma unroll
        for (int j = 0; j < 4; j++) {
            eji[j]    = ev[j] + (gji[j] - m1) * is1 * gg[j] + gb[j];
            float eik = ev[j] + (gik[j] - m2) * is2 * gg[j] + gb[j];
            sg1[j] = __fdividef(1.f, 1.f + __expf(-eji[j])); t1 += sg1[j];
            sg2[j] = __fdividef(1.f, 1.f + __expf(-eik));    t2 += sg2[j];
        }
        #pragma unroll
        for (int o = 16; o; o >>= 1) {
            t1 += __shfl_xor_sync(0xffffffffu, t1, o);
            t2 += __shfl_xor_sync(0xffffffffu, t2, o);
        }
        float w1 = __fdividef(1.f, t1 + 1e-6f);
        float w2 = __fdividef(1.f, t2 + 1e-6f);

        float mji[4], mik[4];
        #pragma unroll
        for (int j = 0; j < 4; j++) {
            mji[j] = a2r[j] * sg1[j] * w1;
            mik[j] = a3c[j] * sg2[j] * w2;
        }
        red_add_v4(acc + co, mji);
        red_add_v4(acc + ro, mik);
        st4_h(e + eo, eji, pef);
    }
}

// ---------------- fused final scorer: ec GEMM + relu-dot (cp.async pipelined) ----------
__global__ void __launch_bounds__(256, 2) final_fused_kernel(
    const int* __restrict__ rows, const int* __restrict__ cols,
    const float* __restrict__ ha, const float* __restrict__ hb,
    const float* __restrict__ e, const float* __restrict__ W,
    const float* __restrict__ s1b, const float* __restrict__ s2w,
    const float* __restrict__ s2b, float* __restrict__ out, int E_)
{
    extern __shared__ float sm[];
    uint32_t* as  = reinterpret_cast<uint32_t*>(sm);
    uint32_t* wsm = reinterpret_cast<uint32_t*>(sm + SM_W);
    const int t = threadIdx.x;
    const int wid = t >> 5, lane = t & 31;
    const int brow = blockIdx.x * 128;

    load_tile_tf32(e, E_, brow, as, t, 1);
    float dacc[2][8][4];
    gemm_core_256(as, wsm, W, dacc, t);
    __syncthreads();
    float* ebt = sm;
    store_dacc_smem(ebt, dacc, nullptr, t);
    __syncthreads();

    int idx;
    {
        int epos = brow + wid * 16 + (lane & 15);
        if (epos >= E_) epos = E_ - 1;
        const int* bp = (lane < 16) ? rows : cols;
        idx = bp[epos];
    }

    const uint32_t pfw = smem_u32(sm) + (uint32_t)SM_W * 4 + (uint32_t)wid * 2048;
    const uint32_t loff = (uint32_t)lane * 16;

    {
        int r0 = __shfl_sync(0xffffffffu, idx, 0);
        int c0 = __shfl_sync(0xffffffffu, idx, 16);
        uint32_t b = pfw + loff;
        cpa16(b,       ha + (size_t)r0 * 128 + lane * 4);
        cpa16(b + 512, hb + (size_t)c0 * 128 + lane * 4);
        cpa_commit();
    }

    float b4[4], wv[4];
    ld4(b4, s1b + lane * 4);
    ld4(wv, s2w + lane * 4);
    const float s2b0 = s2b[0];

    #pragma unroll 1
    for (int i = 0; i < 16; i++) {
        const int le = wid * 16 + i;
        const int w = brow + le;
        if (w >= E_) break;

        {
            const int ipn = (i < 15) ? i + 1 : 15;
            int rn = __shfl_sync(0xffffffffu, idx, ipn);
            int cn = __shfl_sync(0xffffffffu, idx, 16 + ipn);
            uint32_t b = pfw + ((i + 1) & 1) * 1024 + loff;
            cpa16(b,       ha + (size_t)rn * 128 + lane * 4);
            cpa16(b + 512, hb + (size_t)cn * 128 + lane * 4);
            cpa_commit();
        }

        float C[4];
        ld4(C, ebt + le * AS_STRIDE + lane * 4);

        cpa_wait1();
        float A[4], B[4];
        const uint32_t bb = pfw + (i & 1) * 1024 + loff;
        lds4(A, bb);
        lds4(B, bb + 512);

        float p = 0.f;
        #pragma unroll
        for (int j = 0; j < 4; j++) {
            float u = fmaxf(A[j] + B[j] + C[j] + b4[j], 0.f);
            p = fmaf(u, wv[j], p);
        }
        #pragma unroll
        for (int o = 16; o; o >>= 1) p += __shfl_xor_sync(0xffffffffu, p, o);
        if (lane == 0) out[w] = p + s2b0;
    }
}

// ---------------- zero ----------------
__global__ void zero_kernel(float* __restrict__ p, int n) {
    int i = (blockIdx.x * blockDim.x + threadIdx.x) * 4;
    if (i < n) *reinterpret_cast<float4*>(p + i) = make_float4(0.f, 0.f, 0.f, 0.f);
}

// ---------------- node update: h += LN(relu(A1h + acc)); acc = 0 ----------------
__global__ void __launch_bounds__(256) node_update_kernel(
    const float* __restrict__ A1, float* __restrict__ acc, float* __restrict__ h,
    const float* __restrict__ lng, const float* __restrict__ lnb, int M)
{
    const int w = blockIdx.x * 8 + (threadIdx.x >> 5);
    const int lane = threadIdx.x & 31;
    if (w >= M) return;
    const size_t off = (size_t)w * 128 + lane * 4;
    float a[4], cc[4], t[4];
    ld4(a, A1 + off); ld4(cc, acc + off);
    float s = 0.f, q = 0.f;
    #pragma unroll
    for (int i = 0; i < 4; i++) {
        t[i] = fmaxf(a[i] + cc[i], 0.f);
        s += t[i]; q = fmaf(t[i], t[i], q);
    }
    #pragma unroll
    for (int o = 16; o; o >>= 1) {
        s += __shfl_xor_sync(0xffffffffu, s, o);
        q += __shfl_xor_sync(0xffffffffu, q, o);
    }
    const float inv = 1.f / 128.f;
    float m = s * inv;
    float is = rsqrtf(fmaxf(q * inv - m * m, 0.f) + 1e-5f);
    float gg[4], gb[4], hv[4];
    ld4(gg, lng + lane * 4); ld4(gb, lnb + lane * 4);
    ld4(hv, h + off);
    #pragma unroll
    for (int i = 0; i < 4; i++) hv[i] += (t[i] - m) * is * gg[i] + gb[i];
    st4(h + off, hv);
    float z[4] = {0.f, 0.f, 0.f, 0.f};
    st4(acc + off, z);
}

// ---------------- host ----------------
extern "C" void kernel_launch(void* const* d_in, const int* in_sizes, int n_in,
                              void* d_out, int out_size)
{
    const float* x    = (const float*)d_in[0];
    const float* ea   = (const float*)d_in[1];
    const int*   ei   = (const int*)  d_in[2];
    const float* W11w = (const float*)d_in[3];
    const float* W11b = (const float*)d_in[4];
    const float* W12w = (const float*)d_in[5];
    const float* W12b = (const float*)d_in[6];
    const float* W21w = (const float*)d_in[7];
    const float* W21b = (const float*)d_in[8];
    const float* W22w = (const float*)d_in[9];
    const float* W22b = (const float*)d_in[10];
    const float* ln1g = (const float*)d_in[11];
    const float* ln1b = (const float*)d_in[12];
    const float* ln2g = (const float*)d_in[13];
    const float* ln2b = (const float*)d_in[14];
    const float* Aw   = (const float*)d_in[15];
    const float* Ab   = (const float*)d_in[16];
    const float* Bw   = (const float*)d_in[17];
    const float* Bb   = (const float*)d_in[18];
    const float* lnhg = (const float*)d_in[19];
    const float* lnhb = (const float*)d_in[20];
    const float* lneg = (const float*)d_in[21];
    const float* lneb = (const float*)d_in[22];
    const float* s1w  = (const float*)d_in[23];
    const float* s1b  = (const float*)d_in[24];
    const float* s2w  = (const float*)d_in[25];
    const float* s2b  = (const float*)d_in[26];

    int Nn = in_sizes[0] / 64;
    int Ee = in_sizes[2] / 2;
    if (Nn > CAP_N) Nn = CAP_N;
    if (Ee > CAP_E) Ee = CAP_E;

    float *ph, *pacc, *pA1, *pA2, *pA3, *pB2, *pB3, *pe, *ptmp, *pwc;
    cudaGetSymbolAddress((void**)&ph,   g_h);
    cudaGetSymbolAddress((void**)&pacc, g_acc);
    cudaGetSymbolAddress((void**)&pA1,  g_A1);
    cudaGetSymbolAddress((void**)&pA2,  g_A2);
    cudaGetSymbolAddress((void**)&pA3,  g_A3);
    cudaGetSymbolAddress((void**)&pB2,  g_B2);
    cudaGetSymbolAddress((void**)&pB3,  g_B3);
    cudaGetSymbolAddress((void**)&pe,   g_e);
    cudaGetSymbolAddress((void**)&ptmp, g_tmp);
    cudaGetSymbolAddress((void**)&pwc,  g_wc);

    // pre-converted tf32 weight regions
    float* wcW12 = pwc;                 // 16384
    float* wcW22 = pwc + 16384;         // 16384
    float* wcAw  = pwc + 32768;         // 147456
    float* wcBw  = wcAw + 147456;       // 147456
    float* wcS1  = wcBw + 147456;       // 49152

    conv_tf32_kernel<<<16, 256>>>(W12w, wcW12, 4096);
    conv_tf32_kernel<<<16, 256>>>(W22w, wcW22, 4096);
    conv_tf32_kernel<<<144, 256>>>(Aw, wcAw, 36864);
    conv_tf32_kernel<<<144, 256>>>(Bw, wcBw, 36864);
    conv_tf32_kernel<<<48, 256>>>(s1w, wcS1, 12288);

    cudaFuncSetAttribute(gemm_mma_kernel,    cudaFuncAttributeMaxDynamicSharedMemorySize, SM_BYTES);
    cudaFuncSetAttribute(edge_fused_kernel,  cudaFuncAttributeMaxDynamicSharedMemorySize, SM_BYTES);
    cudaFuncSetAttribute(final_fused_kernel, cudaFuncAttributeMaxDynamicSharedMemorySize, SM_BYTES);

    auto gemm_tc = [&](const float* A, G5& g, int M) {
        int tiles = (M + 127) / 128;
        dim3 grid(tiles, g.nw);
        gemm_mma_kernel<<<grid, 256, SM_BYTES>>>(A, g, M);
    };
    auto gemm1 = [&](const float* A, const float* W, const float* b, float* o, int M,
                     int ih, int oh) {
        G5 g; g.nw = 1; g.W[0] = W; g.B[0] = b; g.O[0] = o; g.OH[0] = oh; g.IH = ih;
        gemm_tc(A, g, M);
    };

    const int etiles = (Ee + 127) / 128;

    // node embed: h = LN(relu(x@W11+b)) @ W12 + b     (uses acc as temp)
    embed_ln_kernel<<<(Nn + 7) / 8, 256>>>(x, W11w, W11b, ln1g, ln1b, pacc, Nn, 64);
    gemm1(pacc, wcW12, W12b, ph, Nn, 0, 0);
    // edge embed: e = LN(relu(ea@W21+b)) @ W22 + b
    embed_ln_kernel<<<(Ee + 7) / 8, 256>>>(ea, W21w, W21b, ln2g, ln2b, ptmp, Ee, 32);
    gemm1(ptmp, wcW22, W22b, pe, Ee, 1, 1);

    // zero the scatter accumulator
    zero_kernel<<<(Nn * 128 / 4 + 255) / 256, 256>>>(pacc, Nn * 128);

    for (int l = 0; l < 3; l++) {
        const float* Awl = wcAw + (size_t)l * 3 * 128 * 128;
        const float* Abl = Ab + (size_t)l * 3 * 128;
        const float* Bwl = wcBw + (size_t)l * 3 * 128 * 128;
        const float* Bbl = Bb + (size_t)l * 3 * 128;
        {
            G5 g; g.nw = 5; g.IH = 0;
            g.W[0] = Awl;          g.B[0] = Abl;        g.O[0] = pA1; g.OH[0] = 0;
            g.W[1] = Awl + 16384;  g.B[1] = Abl + 128;  g.O[1] = pA2; g.OH[1] = 2;
            g.W[2] = Awl + 32768;  g.B[2] = Abl + 256;  g.O[2] = pA3; g.OH[2] = 2;
            g.W[3] = Bwl + 16384;  g.B[3] = Bbl + 128;  g.O[3] = pB2; g.OH[3] = 2;
            g.W[4] = Bwl + 32768;  g.B[4] = Bbl + 256;  g.O[4] = pB3; g.OH[4] = 2;
            gemm_tc(ph, g, Nn);
        }
        edge_fused_kernel<<<etiles, 256, SM_BYTES>>>(
            ei, ei + Ee, pe, Bwl, Bbl, pA2, pA3, pB2, pB3,
            lneg + l * 128, lneb + l * 128, pacc, Ee);
        node_update_kernel<<<(Nn + 7) / 8, 256>>>(pA1, pacc, ph,
                                                  lnhg + l * 128, lnhb + l * 128, Nn);
    }

    // final scorer: score = relu(h[row]@Sa + h[col]@Sb + e@Sc + s1b) @ s2w + s2b
    {
        G5 g; g.nw = 2; g.IH = 0;
        g.W[0] = wcS1;          g.B[0] = nullptr; g.O[0] = pA1; g.OH[0] = 2;
        g.W[1] = wcS1 + 16384;  g.B[1] = nullptr; g.O[1] = pA2; g.OH[1] = 2;
        gemm_tc(ph, g, Nn);
    }
    final_fused_kernel<<<etiles, 256, SM_BYTES>>>(
        ei, ei + Ee, pA1, pA2, pe, wcS1 + 32768, s1b, s2w, s2b, (float*)d_out, Ee);
}

// round 16
// speedup vs baseline: 1.0511x; 1.0511x over previous
#include <cuda_runtime.h>
#include <cstdint>

#define H128 128
static const int CAP_N = 50000;
static const int CAP_E = 800000;

// ---------------- scratch (device globals; no allocation allowed) ----------------
__device__ float g_h  [CAP_N * H128];
__device__ float g_acc[CAP_N * H128];
__device__ float g_A1 [CAP_N * H128];
__device__ float g_A2 [CAP_N * H128];
__device__ float g_A3 [CAP_N * H128];
__device__ float g_B2 [CAP_N * H128];
__device__ float g_B3 [CAP_N * H128];
__device__ float g_e  [CAP_E * H128];
__device__ float g_tmp[CAP_E * H128];
__device__ float g_wc [376832];          // pre-converted tf32 weights

// ---------------- L2 residency policies ----------------
__device__ __forceinline__ uint64_t pol_ef() {
    uint64_t p;
    asm("createpolicy.fractional.L2::evict_first.b64 %0, 1.0;" : "=l"(p));
    return p;
}
__device__ __forceinline__ uint64_t pol_el() {
    uint64_t p;
    asm("createpolicy.fractional.L2::evict_last.b64 %0, 1.0;" : "=l"(p));
    return p;
}

// ---------------- generic helpers ----------------
__device__ __forceinline__ uint32_t smem_u32(const void* p) {
    uint32_t a;
    asm("{ .reg .u64 t; cvta.to.shared.u64 t, %1; cvt.u32.u64 %0, t; }" : "=r"(a) : "l"(p));
    return a;
}
__device__ __forceinline__ void red_add_v4(float* p, const float* v) {
    asm volatile("red.global.add.v4.f32 [%0], {%1, %2, %3, %4};"
                 :: "l"(p), "f"(v[0]), "f"(v[1]), "f"(v[2]), "f"(v[3]) : "memory");
}
__device__ __forceinline__ void ld4(float* d, const float* p) {
    float4 v = *reinterpret_cast<const float4*>(p);
    d[0] = v.x; d[1] = v.y; d[2] = v.z; d[3] = v.w;
}
__device__ __forceinline__ void ld4_h(float* d, const float* p, uint64_t pol) {
    asm volatile("ld.global.L2::cache_hint.v4.f32 {%0,%1,%2,%3}, [%4], %5;"
                 : "=f"(d[0]), "=f"(d[1]), "=f"(d[2]), "=f"(d[3]) : "l"(p), "l"(pol));
}
__device__ __forceinline__ void lds4(float* d, uint32_t a) {
    asm volatile("ld.shared.v4.f32 {%0,%1,%2,%3}, [%4];"
                 : "=f"(d[0]), "=f"(d[1]), "=f"(d[2]), "=f"(d[3]) : "r"(a));
}
__device__ __forceinline__ void st4(float* p, const float* d) {
    float4 v; v.x = d[0]; v.y = d[1]; v.z = d[2]; v.w = d[3];
    *reinterpret_cast<float4*>(p) = v;
}
__device__ __forceinline__ void st4_h(float* p, const float* d, uint64_t pol) {
    asm volatile("st.global.L2::cache_hint.v4.f32 [%0], {%1,%2,%3,%4}, %5;"
                 :: "l"(p), "f"(d[0]), "f"(d[1]), "f"(d[2]), "f"(d[3]), "l"(pol) : "memory");
}
__device__ __forceinline__ void st2_h(float* p, float a, float b, int hint) {
    if (hint == 2) {
        uint64_t pol = pol_el();
        asm volatile("st.global.L2::cache_hint.v2.f32 [%0], {%1,%2}, %3;"
                     :: "l"(p), "f"(a), "f"(b), "l"(pol) : "memory");
    } else if (hint == 1) {
        uint64_t pol = pol_ef();
        asm volatile("st.global.L2::cache_hint.v2.f32 [%0], {%1,%2}, %3;"
                     :: "l"(p), "f"(a), "f"(b), "l"(pol) : "memory");
    } else {
        float2 v; v.x = a; v.y = b;
        *reinterpret_cast<float2*>(p) = v;
    }
}
// 16B async copy gmem->smem (plain form: cache_hint on LDGSTS traps on sm_103)
__device__ __forceinline__ void cpa16(uint32_t dst, const float* src) {
    asm volatile("cp.async.ca.shared.global [%0], [%1], 16;"
                 :: "r"(dst), "l"(src) : "memory");
}
__device__ __forceinline__ void cpa_commit() {
    asm volatile("cp.async.commit_group;" ::: "memory");
}
__device__ __forceinline__ void cpa_wait1() {
    asm volatile("cp.async.wait_group 1;" ::: "memory");
}
__device__ __forceinline__ void cpa_wait0() {
    asm volatile("cp.async.wait_group 0;" ::: "memory");
}
__device__ __forceinline__ uint32_t to_tf32(float x) {
    uint32_t r;
    asm("cvt.rna.tf32.f32 %0, %1;" : "=r"(r) : "f"(x));
    return r;
}
__device__ __forceinline__ void mma_tf32(float d[4], const uint32_t a[4], const uint32_t b[2],
                                         const float c[4]) {
    asm volatile(
        "mma.sync.aligned.m16n8k8.row.col.f32.tf32.tf32.f32 "
        "{%0,%1,%2,%3}, {%4,%5,%6,%7}, {%8,%9}, {%10,%11,%12,%13};"
        : "=f"(d[0]), "=f"(d[1]), "=f"(d[2]), "=f"(d[3])
        : "r"(a[0]), "r"(a[1]), "r"(a[2]), "r"(a[3]),
          "r"(b[0]), "r"(b[1]),
          "f"(c[0]), "f"(c[1]), "f"(c[2]), "f"(c[3]));
}

// ---------------- weight pre-conversion to tf32 ----------------
__global__ void conv_tf32_kernel(const float* __restrict__ src, float* __restrict__ dst, int n4) {
    int i = blockIdx.x * 256 + threadIdx.x;
    if (i < n4) {
        float4 v = reinterpret_cast<const float4*>(src)[i];
        uint4 u; u.x = to_tf32(v.x); u.y = to_tf32(v.y); u.z = to_tf32(v.z); u.w = to_tf32(v.w);
        reinterpret_cast<uint4*>(dst)[i] = u;
    }
}

// ---------------- shared GEMM tile machinery (256 threads, 128x128 tile) ----------------
static const int AS_STRIDE = 132;
static const int WS_STRIDE = 136;
static const int SM_W = 128 * AS_STRIDE;            // 16896 floats = 67584 B
static const int W_CHUNK = 32 * WS_STRIDE;          // 4352 floats per 32-k chunk buffer
static const int SM_FLOATS = SM_W + 2 * W_CHUNK;    // + 8704 floats = 34816 B
static const int SM_BYTES = SM_FLOATS * 4;          // 102400 B -> 2 CTAs/SM

__device__ __forceinline__ void load_tile_tf32(const float* __restrict__ A, int M, int brow,
                                               uint32_t* as, int t, int ef) {
    const float4* A4 = reinterpret_cast<const float4*>(A);
    uint64_t pol = ef ? pol_ef() : 0;
    #pragma unroll
    for (int j = 0; j < 16; j++) {
        int flat = j * 256 + t;
        int row = flat >> 5, k4 = flat & 31;
        int gr = brow + row;
        float v[4] = {0.f, 0.f, 0.f, 0.f};
        if (gr < M) {
            const float* p = reinterpret_cast<const float*>(A4 + (size_t)gr * 32 + k4);
            if (ef) ld4_h(v, p, pol); else ld4(v, p);
        }
        uint4 u; u.x = to_tf32(v[0]); u.y = to_tf32(v[1]); u.z = to_tf32(v[2]); u.w = to_tf32(v[3]);
        *reinterpret_cast<uint4*>(as + row * AS_STRIDE + k4 * 4) = u;
    }
}

// async-load one 32-k W chunk (pre-converted tf32) into smem buffer
__device__ __forceinline__ void cpa_chunk_w(uint32_t wb_addr, const float* __restrict__ W,
                                            int ch, int t) {
    #pragma unroll
    for (int j = 0; j < 4; j++) {
        int flat = j * 256 + t;
        int k = flat >> 5, c4 = flat & 31;
        cpa16(wb_addr + (uint32_t)(k * WS_STRIDE + c4 * 4) * 4,
              W + (size_t)(ch * 32 + k) * 128 + c4 * 4);
    }
}

// dacc = Atile @ W ; W pre-converted tf32; 4 x 32-k chunks, cp.async double-buffered.
__device__ __forceinline__ void gemm_core_256(const uint32_t* as, uint32_t* wsm,
                                              const float* __restrict__ W,
                                              float dacc[2][8][4], int t) {
    const int wid = t >> 5, lane = t & 31;
    const int gid = lane >> 2, tig = lane & 3;
    const int m0 = (wid & 3) * 32, n0 = (wid >> 2) * 64;
    const uint32_t wsm_addr = smem_u32(wsm);

    #pragma unroll
    for (int mi = 0; mi < 2; mi++)
        #pragma unroll
        for (int ni = 0; ni < 8; ni++)
            #pragma unroll
            for (int q = 0; q < 4; q++) dacc[mi][ni][q] = 0.f;

    cpa_chunk_w(wsm_addr, W, 0, t);
    cpa_commit();

    #pragma unroll 1
    for (int ch = 0; ch < 4; ch++) {
        if (ch < 3) {
            cpa_chunk_w(wsm_addr + (uint32_t)(((ch + 1) & 1) * W_CHUNK) * 4, W, ch + 1, t);
            cpa_commit();
            cpa_wait1();
        } else {
            cpa_wait0();
        }
        __syncthreads();
        const uint32_t* wb = wsm + (ch & 1) * W_CHUNK;

        #pragma unroll
        for (int ks = 0; ks < 4; ks++) {
            const int k0 = ks * 8;
            uint32_t af[2][4];
            #pragma unroll
            for (int mi = 0; mi < 2; mi++) {
                const uint32_t* pa = as + (m0 + mi * 16 + gid) * AS_STRIDE + ch * 32 + k0;
                af[mi][0] = pa[tig];
                af[mi][1] = pa[8 * AS_STRIDE + tig];
                af[mi][2] = pa[tig + 4];
                af[mi][3] = pa[8 * AS_STRIDE + tig + 4];
            }
            uint32_t bf[8][2];
            #pragma unroll
            for (int ni = 0; ni < 8; ni++) {
                const uint32_t* pb = wb + (k0 + tig) * WS_STRIDE + n0 + ni * 8 + gid;
                bf[ni][0] = pb[0];
                bf[ni][1] = pb[4 * WS_STRIDE];
            }
            #pragma unroll
            for (int mi = 0; mi < 2; mi++)
                #pragma unroll
                for (int ni = 0; ni < 8; ni++)
                    mma_tf32(dacc[mi][ni], af[mi], bf[ni], dacc[mi][ni]);
        }
        __syncthreads();
    }
}

__device__ __forceinline__ void store_dacc_smem(float* ebt, float dacc[2][8][4],
                                                const float* __restrict__ bias, int t) {
    const int wid = t >> 5, lane = t & 31;
    const int gid = lane >> 2, tig = lane & 3;
    const int m0 = (wid & 3) * 32, n0 = (wid >> 2) * 64;
    #pragma unroll
    for (int ni = 0; ni < 8; ni++) {
        const int col = n0 + ni * 8 + 2 * tig;
        float b0 = 0.f, b1 = 0.f;
        if (bias) { b0 = bias[col]; b1 = bias[col + 1]; }
        #pragma unroll
        for (int mi = 0; mi < 2; mi++) {
            const int row = m0 + mi * 16 + gid;
            float2 v0; v0.x = dacc[mi][ni][0] + b0; v0.y = dacc[mi][ni][1] + b1;
            float2 v1; v1.x = dacc[mi][ni][2] + b0; v1.y = dacc[mi][ni][3] + b1;
            *reinterpret_cast<float2*>(ebt + row * AS_STRIDE + col) = v0;
            *reinterpret_cast<float2*>(ebt + (row + 8) * AS_STRIDE + col) = v1;
        }
    }
}

// write (dacc + bias) as tf32 into the A-region smem tile (for chained GEMM)
__device__ __forceinline__ void store_dacc_smem_tf32(uint32_t* as_, float dacc[2][8][4],
                                                     const float* __restrict__ bias, int t) {
    const int wid = t >> 5, lane = t & 31;
    const int gid = lane >> 2, tig = lane & 3;
    const int m0 = (wid & 3) * 32, n0 = (wid >> 2) * 64;
    #pragma unroll
    for (int ni = 0; ni < 8; ni++) {
        const int col = n0 + ni * 8 + 2 * tig;
        float b0 = 0.f, b1 = 0.f;
        if (bias) { b0 = bias[col]; b1 = bias[col + 1]; }
        #pragma unroll
        for (int mi = 0; mi < 2; mi++) {
            const int row = m0 + mi * 16 + gid;
            uint2 v0; v0.x = to_tf32(dacc[mi][ni][0] + b0); v0.y = to_tf32(dacc[mi][ni][1] + b1);
            uint2 v1; v1.x = to_tf32(dacc[mi][ni][2] + b0); v1.y = to_tf32(dacc[mi][ni][3] + b1);
            *reinterpret_cast<uint2*>(as_ + row * AS_STRIDE + col) = v0;
            *reinterpret_cast<uint2*>(as_ + (row + 8) * AS_STRIDE + col) = v1;
        }
    }
}

__device__ __forceinline__ void store_dacc_global(float* O, float dacc[2][8][4],
                                                  const float* __restrict__ bias,
                                                  int brow, int M, int oh, int t) {
    const int wid = t >> 5, lane = t & 31;
    const int gid = lane >> 2, tig = lane & 3;
    const int m0 = (wid & 3) * 32, n0 = (wid >> 2) * 64;
    #pragma unroll
    for (int ni = 0; ni < 8; ni++) {
        const int col = n0 + ni * 8 + 2 * tig;
        float b0 = 0.f, b1 = 0.f;
        if (bias) { b0 = bias[col]; b1 = bias[col + 1]; }
        #pragma unroll
        for (int mi = 0; mi < 2; mi++) {
            const int row0 = brow + m0 + mi * 16 + gid;
            if (row0 < M)
                st2_h(O + (size_t)row0 * 128 + col, dacc[mi][ni][0] + b0, dacc[mi][ni][1] + b1, oh);
            if (row0 + 8 < M)
                st2_h(O + (size_t)(row0 + 8) * 128 + col, dacc[mi][ni][2] + b0, dacc[mi][ni][3] + b1, oh);
        }
    }
}

// ---------------- standalone multi-weight GEMM (weight = blockIdx.y) ----------------
struct G5 {
    const float* W[5];
    const float* B[5];
    float*       O[5];
    int OH[5];
    int nw;
    int IH;
};

__global__ void __launch_bounds__(256, 2) gemm_mma_kernel(
    const float* __restrict__ A, G5 g, int M)
{
    extern __shared__ float sm[];
    uint32_t* as  = reinterpret_cast<uint32_t*>(sm);
    uint32_t* wsm = reinterpret_cast<uint32_t*>(sm + SM_W);
    const int t = threadIdx.x;
    const int brow = blockIdx.x * 128;
    const int w = blockIdx.y;

    load_tile_tf32(A, M, brow, as, t, g.IH);

    float dacc[2][8][4];
    gemm_core_256(as, wsm, g.W[w], dacc, t);
    store_dacc_global(g.O[w], dacc, g.B[w], brow, M, g.OH[w], t);
}

// ---------------- embed stage1: out = LN(relu(in @ W + b)) (warp per row) ----------------
__global__ void __launch_bounds__(256) embed_ln_kernel(
    const float* __restrict__ in, const float* __restrict__ W, const float* __restrict__ bias,
    const float* __restrict__ lng, const float* __restrict__ lnb,
    float* __restrict__ out, int M, int Kin)
{
    const int w = blockIdx.x * 8 + (threadIdx.x >> 5);
    const int lane = threadIdx.x & 31;
    if (w >= M) return;
    const float* xr = in + (size_t)w * Kin;
    float x0 = (lane < Kin) ? xr[lane] : 0.f;
    float x1 = (lane + 32 < Kin) ? xr[lane + 32] : 0.f;

    float a[4];
    ld4(a, bias + lane * 4);
    for (int k = 0; k < Kin; k++) {
        float xk = __shfl_sync(0xffffffffu, (k < 32) ? x0 : x1, k & 31);
        float4 wv = *reinterpret_cast<const float4*>(W + k * 128 + lane * 4);
        a[0] = fmaf(xk, wv.x, a[0]);
        a[1] = fmaf(xk, wv.y, a[1]);
        a[2] = fmaf(xk, wv.z, a[2]);
        a[3] = fmaf(xk, wv.w, a[3]);
    }
    float s = 0.f, q = 0.f;
    #pragma unroll
    for (int i = 0; i < 4; i++) {
        a[i] = fmaxf(a[i], 0.f);
        s += a[i]; q = fmaf(a[i], a[i], q);
    }
    #pragma unroll
    for (int o = 16; o; o >>= 1) {
        s += __shfl_xor_sync(0xffffffffu, s, o);
        q += __shfl_xor_sync(0xffffffffu, q, o);
    }
    const float inv = 1.f / 128.f;
    float m = s * inv;
    float is = rsqrtf(fmaxf(q * inv - m * m, 0.f) + 1e-5f);
    float gg[4], gb[4], o4[4];
    ld4(gg, lng + lane * 4); ld4(gb, lnb + lane * 4);
    #pragma unroll
    for (int i = 0; i < 4; i++) o4[i] = (a[i] - m) * is * gg[i] + gb[i];
    uint64_t pef = pol_ef();
    st4_h(out + (size_t)w * 128 + lane * 4, o4, pef);
}

// ---------------- fused edge layer: [optional W22 pre-GEMM] + B1e GEMM + gated edge update ----
__global__ void __launch_bounds__(256, 2) edge_fused_kernel(
    const int* __restrict__ rows, const int* __restrict__ cols,
    float* __restrict__ e,
    const float* __restrict__ tmp_in, const float* __restrict__ Wpre,
    const float* __restrict__ bpre,
    const float* __restrict__ W, const float* __restrict__ bias,
    const float* __restrict__ A2, const float* __restrict__ A3,
    const float* __restrict__ B2, const float* __restrict__ B3,
    const float* __restrict__ lng, const float* __restrict__ lnb,
    float* __restrict__ acc, int E_)
{
    extern __shared__ float sm[];
    uint32_t* as  = reinterpret_cast<uint32_t*>(sm);
    uint32_t* wsm = reinterpret_cast<uint32_t*>(sm + SM_W);
    const int t = threadIdx.x;
    const int wid = t >> 5, lane = t & 31;
    const int brow = blockIdx.x * 128;

    float dacc[2][8][4];
    if (Wpre) {
        // chained: e_tile = tmp_tile @ Wpre + bpre ; write to global e AND keep tf32 in smem
        load_tile_tf32(tmp_in, E_, brow, as, t, 1);
        gemm_core_256(as, wsm, Wpre, dacc, t);
        store_dacc_global(e, dacc, bpre, brow, E_, 1, t);
        __syncthreads();
        store_dacc_smem_tf32(as, dacc, bpre, t);
        // gemm_core_256's first internal __syncthreads orders these writes vs reads
    } else {
        load_tile_tf32(e, E_, brow, as, t, 1);
    }

    // stage 1: b1e tile = e_tile @ W + bias
    gemm_core_256(as, wsm, W, dacc, t);
    __syncthreads();
    float* ebt = sm;
    store_dacc_smem(ebt, dacc, bias, t);
    __syncthreads();

    // stage 2: warp per edge with cp.async double-buffered B-gather prefetch.
    int idx;
    {
        int epos = brow + wid * 16 + (lane & 15);
        if (epos >= E_) epos = E_ - 1;
        const int* bp = (lane < 16) ? rows : cols;
        idx = bp[epos];
    }

    const uint64_t pef = pol_ef();
    const uint64_t pel = pol_el();
    const uint32_t pfw = smem_u32(sm) + (uint32_t)SM_W * 4 + (uint32_t)wid * 4096;
    const uint32_t loff = (uint32_t)lane * 16;

    {
        int r0 = __shfl_sync(0xffffffffu, idx, 0);
        int c0 = __shfl_sync(0xffffffffu, idx, 16);
        uint32_t b = pfw + loff;
        cpa16(b,        B2 + (size_t)r0 * 128 + lane * 4);
        cpa16(b + 512,  B3 + (size_t)r0 * 128 + lane * 4);
        cpa16(b + 1024, B2 + (size_t)c0 * 128 + lane * 4);
        cpa16(b + 1536, B3 + (size_t)c0 * 128 + lane * 4);
        cpa_commit();
    }

    float gg[4], gb[4];
    ld4(gg, lng + lane * 4); ld4(gb, lnb + lane * 4);
    const float inv = 1.f / 128.f;

    #pragma unroll 1
    for (int i = 0; i < 16; i++) {
        const int le = wid * 16 + i;
        const int w = brow + le;
        if (w >= E_) break;
        const int r = __shfl_sync(0xffffffffu, idx, i);
        const int c = __shfl_sync(0xffffffffu, idx, 16 + i);

        {
            const int ipn = (i < 15) ? i + 1 : 15;
            int rn = __shfl_sync(0xffffffffu, idx, ipn);
            int cn = __shfl_sync(0xffffffffu, idx, 16 + ipn);
            uint32_t b = pfw + ((i + 1) & 1) * 2048 + loff;
            cpa16(b,        B2 + (size_t)rn * 128 + lane * 4);
            cpa16(b + 512,  B3 + (size_t)rn * 128 + lane * 4);
            cpa16(b + 1024, B2 + (size_t)cn * 128 + lane * 4);
            cpa16(b + 1536, B3 + (size_t)cn * 128 + lane * 4);
            cpa_commit();
        }

        const size_t eo = (size_t)w * 128 + lane * 4;
        const size_t ro = (size_t)r * 128 + lane * 4;
        const size_t co = (size_t)c * 128 + lane * 4;

        float a2r[4], a3c[4], ev[4], b1[4];
        ld4_h(a2r, A2 + ro, pel);
        ld4_h(a3c, A3 + co, pel);
        ld4_h(ev, e + eo, pef);
        ld4(b1, ebt + le * AS_STRIDE + lane * 4);

        cpa_wait1();
        float b2r[4], b3r[4], b2c[4], b3c[4];
        const uint32_t bb = pfw + (i & 1) * 2048 + loff;
        lds4(b2r, bb);
        lds4(b3r, bb + 512);
        lds4(b2c, bb + 1024);
        lds4(b3c, bb + 1536);

        float gji[4], gik[4];
        float s1 = 0.f, q1 = 0.f, s2 = 0.f, q2 = 0.f;
        #pragma unroll
        for (int j = 0; j < 4; j++) {
            float u = fmaxf(b1[j] + b2r[j] + b3c[j], 0.f);
            float v = fmaxf(b1[j] + b2c[j] + b3r[j], 0.f);
            gji[j] = u; gik[j] = v;
            s1 += u; q1 = fmaf(u, u, q1);
            s2 += v; q2 = fmaf(v, v, q2);
        }
        #pragma unroll
        for (int o = 16; o; o >>= 1) {
            s1 += __shfl_xor_sync(0xffffffffu, s1, o);
            q1 += __shfl_xor_sync(0xffffffffu, q1, o);
            s2 += __shfl_xor_sync(0xffffffffu, s2, o);
            q2 += __shfl_xor_sync(0xffffffffu, q2, o);
        }
        float m1 = s1 * inv, m2 = s2 * inv;
        float is1 = rsqrtf(fmaxf(q1 * inv - m1 * m1, 0.f) + 1e-5f);
        float is2 = rsqrtf(fmaxf(q2 * inv - m2 * m2, 0.f) + 1e-5f);

        float eji[4], sg1[4], sg2[4];
        float t1 = 0.f, t2 = 0.f;
        #pragma unroll
        for (int j = 0; j < 4; j++) {
            eji[j]    = ev[j] + (gji[j] - m1) * is1 * gg[j] + gb[j];
            float eik = ev[j] + (gik[j] - m2) * is2 * gg[j] + gb[j];
            sg1[j] = __fdividef(1.f, 1.f + __expf(-eji[j])); t1 += sg1[j];
            sg2[j] = __fdividef(1.f, 1.f + __expf(-eik));    t2 += sg2[j];
        }
        #pragma unroll
        for (int o = 16; o; o >>= 1) {
            t1 += __shfl_xor_sync(0xffffffffu, t1, o);
            t2 += __shfl_xor_sync(0xffffffffu, t2, o);
        }
        float w1 = __fdividef(1.f, t1 + 1e-6f);
        float w2 = __fdividef(1.f, t2 + 1e-6f);

        float mji[4], mik[4];
        #pragma unroll
        for (int j = 0; j < 4; j++) {
            mji[j] = a2r[j] * sg1[j] * w1;
            mik[j] = a3c[j] * sg2[j] * w2;
        }
        red_add_v4(acc + co, mji);
        red_add_v4(acc + ro, mik);
        st4_h(e + eo, eji, pef);
    }
}

// ---------------- fused final scorer: ec GEMM + relu-dot (cp.async pipelined) ----------
__global__ void __launch_bounds__(256, 2) final_fused_kernel(
    const int* __restrict__ rows, const int* __restrict__ cols,
    const float* __restrict__ ha, const float* __restrict__ hb,
    const float* __restrict__ e, const float* __restrict__ W,
    const float* __restrict__ s1b, const float* __restrict__ s2w,
    const float* __restrict__ s2b, float* __restrict__ out, int E_)
{
    extern __shared__ float sm[];
    uint32_t* as  = reinterpret_cast<uint32_t*>(sm);
    uint32_t* wsm = reinterpret_cast<uint32_t*>(sm + SM_W);
    const int t = threadIdx.x;
    const int wid = t >> 5, lane = t & 31;
    const int brow = blockIdx.x * 128;

    load_tile_tf32(e, E_, brow, as, t, 1);
    float dacc[2][8][4];
    gemm_core_256(as, wsm, W, dacc, t);
    __syncthreads();
    float* ebt = sm;
    store_dacc_smem(ebt, dacc, nullptr, t);
    __syncthreads();

    int idx;
    {
        int epos = brow + wid * 16 + (lane & 15);
        if (epos >= E_) epos = E_ - 1;
        const int* bp = (lane < 16) ? rows : cols;
        idx = bp[epos];
    }

    const uint32_t pfw = smem_u32(sm) + (uint32_t)SM_W * 4 + (uint32_t)wid * 2048;
    const uint32_t loff = (uint32_t)lane * 16;

    {
        int r0 = __shfl_sync(0xffffffffu, idx, 0);
        int c0 = __shfl_sync(0xffffffffu, idx, 16);
        uint32_t b = pfw + loff;
        cpa16(b,       ha + (size_t)r0 * 128 + lane * 4);
        cpa16(b + 512, hb + (size_t)c0 * 128 + lane * 4);
        cpa_commit();
    }

    float b4[4], wv[4];
    ld4(b4, s1b + lane * 4);
    ld4(wv, s2w + lane * 4);
    const float s2b0 = s2b[0];

    #pragma unroll 1
    for (int i = 0; i < 16; i++) {
        const int le = wid * 16 + i;
        const int w = brow + le;
        if (w >= E_) break;

        {
            const int ipn = (i < 15) ? i + 1 : 15;
            int rn = __shfl_sync(0xffffffffu, idx, ipn);
            int cn = __shfl_sync(0xffffffffu, idx, 16 + ipn);
            uint32_t b = pfw + ((i + 1) & 1) * 1024 + loff;
            cpa16(b,       ha + (size_t)rn * 128 + lane * 4);
            cpa16(b + 512, hb + (size_t)cn * 128 + lane * 4);
            cpa_commit();
        }

        float C[4];
        ld4(C, ebt + le * AS_STRIDE + lane * 4);

        cpa_wait1();
        float A[4], B[4];
        const uint32_t bb = pfw + (i & 1) * 1024 + loff;
        lds4(A, bb);
        lds4(B, bb + 512);

        float p = 0.f;
        #pragma unroll
        for (int j = 0; j < 4; j++) {
            float u = fmaxf(A[j] + B[j] + C[j] + b4[j], 0.f);
            p = fmaf(u, wv[j], p);
        }
        #pragma unroll
        for (int o = 16; o; o >>= 1) p += __shfl_xor_sync(0xffffffffu, p, o);
        if (lane == 0) out[w] = p + s2b0;
    }
}

// ---------------- zero ----------------
__global__ void zero_kernel(float* __restrict__ p, int n) {
    int i = (blockIdx.x * blockDim.x + threadIdx.x) * 4;
    if (i < n) *reinterpret_cast<float4*>(p + i) = make_float4(0.f, 0.f, 0.f, 0.f);
}

// ---------------- node update: h += LN(relu(A1h + acc)); acc = 0 ----------------
__global__ void __launch_bounds__(256) node_update_kernel(
    const float* __restrict__ A1, float* __restrict__ acc, float* __restrict__ h,
    const float* __restrict__ lng, const float* __restrict__ lnb, int M)
{
    const int w = blockIdx.x * 8 + (threadIdx.x >> 5);
    const int lane = threadIdx.x & 31;
    if (w >= M) return;
    const size_t off = (size_t)w * 128 + lane * 4;
    float a[4], cc[4], t[4];
    ld4(a, A1 + off); ld4(cc, acc + off);
    float s = 0.f, q = 0.f;
    #pragma unroll
    for (int i = 0; i < 4; i++) {
        t[i] = fmaxf(a[i] + cc[i], 0.f);
        s += t[i]; q = fmaf(t[i], t[i], q);
    }
    #pragma unroll
    for (int o = 16; o; o >>= 1) {
        s += __shfl_xor_sync(0xffffffffu, s, o);
        q += __shfl_xor_sync(0xffffffffu, q, o);
    }
    const float inv = 1.f / 128.f;
    float m = s * inv;
    float is = rsqrtf(fmaxf(q * inv - m * m, 0.f) + 1e-5f);
    float gg[4], gb[4], hv[4];
    ld4(gg, lng + lane * 4); ld4(gb, lnb + lane * 4);
    ld4(hv, h + off);
    #pragma unroll
    for (int i = 0; i < 4; i++) hv[i] += (t[i] - m) * is * gg[i] + gb[i];
    st4(h + off, hv);
    float z[4] = {0.f, 0.f, 0.f, 0.f};
    st4(acc + off, z);
}

// ---------------- host ----------------
extern "C" void kernel_launch(void* const* d_in, const int* in_sizes, int n_in,
                              void* d_out, int out_size)
{
    const float* x    = (const float*)d_in[0];
    const float* ea   = (const float*)d_in[1];
    const int*   ei   = (const int*)  d_in[2];
    const float* W11w = (const float*)d_in[3];
    const float* W11b = (const float*)d_in[4];
    const float* W12w = (const float*)d_in[5];
    const float* W12b = (const float*)d_in[6];
    const float* W21w = (const float*)d_in[7];
    const float* W21b = (const float*)d_in[8];
    const float* W22w = (const float*)d_in[9];
    const float* W22b = (const float*)d_in[10];
    const float* ln1g = (const float*)d_in[11];
    const float* ln1b = (const float*)d_in[12];
    const float* ln2g = (const float*)d_in[13];
    const float* ln2b = (const float*)d_in[14];
    const float* Aw   = (const float*)d_in[15];
    const float* Ab   = (const float*)d_in[16];
    const float* Bw   = (const float*)d_in[17];
    const float* Bb   = (const float*)d_in[18];
    const float* lnhg = (const float*)d_in[19];
    const float* lnhb = (const float*)d_in[20];
    const float* lneg = (const float*)d_in[21];
    const float* lneb = (const float*)d_in[22];
    const float* s1w  = (const float*)d_in[23];
    const float* s1b  = (const float*)d_in[24];
    const float* s2w  = (const float*)d_in[25];
    const float* s2b  = (const float*)d_in[26];

    int Nn = in_sizes[0] / 64;
    int Ee = in_sizes[2] / 2;
    if (Nn > CAP_N) Nn = CAP_N;
    if (Ee > CAP_E) Ee = CAP_E;

    float *ph, *pacc, *pA1, *pA2, *pA3, *pB2, *pB3, *pe, *ptmp, *pwc;
    cudaGetSymbolAddress((void**)&ph,   g_h);
    cudaGetSymbolAddress((void**)&pacc, g_acc);
    cudaGetSymbolAddress((void**)&pA1,  g_A1);
    cudaGetSymbolAddress((void**)&pA2,  g_A2);
    cudaGetSymbolAddress((void**)&pA3,  g_A3);
    cudaGetSymbolAddress((void**)&pB2,  g_B2);
    cudaGetSymbolAddress((void**)&pB3,  g_B3);
    cudaGetSymbolAddress((void**)&pe,   g_e);
    cudaGetSymbolAddress((void**)&ptmp, g_tmp);
    cudaGetSymbolAddress((void**)&pwc,  g_wc);

    // pre-converted tf32 weight regions
    float* wcW12 = pwc;                 // 16384
    float* wcW22 = pwc + 16384;         // 16384
    float* wcAw  = pwc + 32768;         // 147456
    float* wcBw  = wcAw + 147456;       // 147456
    float* wcS1  = wcBw + 147456;       // 49152

    conv_tf32_kernel<<<16, 256>>>(W12w, wcW12, 4096);
    conv_tf32_kernel<<<16, 256>>>(W22w, wcW22, 4096);
    conv_tf32_kernel<<<144, 256>>>(Aw, wcAw, 36864);
    conv_tf32_kernel<<<144, 256>>>(Bw, wcBw, 36864);
    conv_tf32_kernel<<<48, 256>>>(s1w, wcS1, 12288);

    cudaFuncSetAttribute(gemm_mma_kernel,    cudaFuncAttributeMaxDynamicSharedMemorySize, SM_BYTES);
    cudaFuncSetAttribute(edge_fused_kernel,  cudaFuncAttributeMaxDynamicSharedMemorySize, SM_BYTES);
    cudaFuncSetAttribute(final_fused_kernel, cudaFuncAttributeMaxDynamicSharedMemorySize, SM_BYTES);

    auto gemm_tc = [&](const float* A, G5& g, int M) {
        int tiles = (M + 127) / 128;
        dim3 grid(tiles, g.nw);
        gemm_mma_kernel<<<grid, 256, SM_BYTES>>>(A, g, M);
    };
    auto gemm1 = [&](const float* A, const float* W, const float* b, float* o, int M,
                     int ih, int oh) {
        G5 g; g.nw = 1; g.W[0] = W; g.B[0] = b; g.O[0] = o; g.OH[0] = oh; g.IH = ih;
        gemm_tc(A, g, M);
    };

    const int etiles = (Ee + 127) / 128;

    // node embed: h = LN(relu(x@W11+b)) @ W12 + b     (uses acc as temp)
    embed_ln_kernel<<<(Nn + 7) / 8, 256>>>(x, W11w, W11b, ln1g, ln1b, pacc, Nn, 64);
    gemm1(pacc, wcW12, W12b, ph, Nn, 0, 0);
    // edge embed stage 1 only: tmp = LN(relu(ea@W21+b)); the W22 GEMM is chained
    // into layer-0's edge_fused kernel (saves one full E-sized tmp read pass).
    embed_ln_kernel<<<(Ee + 7) / 8, 256>>>(ea, W21w, W21b, ln2g, ln2b, ptmp, Ee, 32);

    // zero the scatter accumulator
    zero_kernel<<<(Nn * 128 / 4 + 255) / 256, 256>>>(pacc, Nn * 128);

    for (int l = 0; l < 3; l++) {
        const float* Awl = wcAw + (size_t)l * 3 * 128 * 128;
        const float* Abl = Ab + (size_t)l * 3 * 128;
        const float* Bwl = wcBw + (size_t)l * 3 * 128 * 128;
        const float* Bbl = Bb + (size_t)l * 3 * 128;
        {
            G5 g; g.nw = 5; g.IH = 0;
            g.W[0] = Awl;          g.B[0] = Abl;        g.O[0] = pA1; g.OH[0] = 0;
            g.W[1] = Awl + 16384;  g.B[1] = Abl + 128;  g.O[1] = pA2; g.OH[1] = 2;
            g.W[2] = Awl + 32768;  g.B[2] = Abl + 256;  g.O[2] = pA3; g.OH[2] = 2;
            g.W[3] = Bwl + 16384;  g.B[3] = Bbl + 128;  g.O[3] = pB2; g.OH[3] = 2;
            g.W[4] = Bwl + 32768;  g.B[4] = Bbl + 256;  g.O[4] = pB3; g.OH[4] = 2;
            gemm_tc(ph, g, Nn);
        }
        edge_fused_kernel<<<etiles, 256, SM_BYTES>>>(
            ei, ei + Ee, pe,
            (l == 0) ? ptmp : nullptr, (l == 0) ? wcW22 : nullptr,
            (l == 0) ? W22b : nullptr,
            Bwl, Bbl, pA2, pA3, pB2, pB3,
            lneg + l * 128, lneb + l * 128, pacc, Ee);
        node_update_kernel<<<(Nn + 7) / 8, 256>>>(pA1, pacc, ph,
                                                  lnhg + l * 128, lnhb + l * 128, Nn);
    }

    // final scorer: score = relu(h[row]@Sa + h[col]@Sb + e@Sc + s1b) @ s2w + s2b
    {
        G5 g; g.nw = 2; g.IH = 0;
        g.W[0] = wcS1;          g.B[0] = nullptr; g.O[0] = pA1; g.OH[0] = 2;
        g.W[1] = wcS1 + 16384;  g.B[1] = nullptr; g.O[1] = pA2; g.OH[1] = 2;
        gemm_tc(ph, g, Nn);
    }
    final_fused_kernel<<<etiles, 256, SM_BYTES>>>(
        ei, ei + Ee, pA1, pA2, pe, wcS1 + 32768, s1b, s2w, s2b, (float*)d_out, Ee);
}